// round 5
// baseline (speedup 1.0000x reference)
#include <cuda_runtime.h>

#define NN 8192
#define EE 16384
#define EE4 (EE / 4)   // 4096 float4 per row

// u = e .* (Ro^T a)  in g_uv[0..EE), v = e .* (Ri^T b) in g_uv[EE..2EE).
// Zeroed each launch via a cudaMemsetAsync node (single contiguous region).
__device__ float g_uv[2 * EE];

// ---------------- Phase 1: column reductions -------------------------------
// u[e] = ev[e] * sum_n Ro[n,e]*a[n],  v[e] = ev[e] * sum_n Ri[n,e]*b[n]
// where a = X.k0, b = X.k1 (computed inline per block from X — L2-resident).
// 128 threads/block; each thread owns 4 consecutive columns (one float4).
// Block covers 512 columns x 128 rows = 0.5 MB of each-matrix traffic.
__global__ __launch_bounds__(128) void phase1(
    const float4* __restrict__ X4, const float* __restrict__ ker,
    const float4* __restrict__ Ri4, const float4* __restrict__ Ro4,
    const float4* __restrict__ ev4)
{
    __shared__ float sa[128], sb[128];
    int tid = threadIdx.x;
    int e4  = blockIdx.x * 128 + tid;     // float4 column index
    int n0  = blockIdx.y * 128;           // row chunk base

    {   // a,b for this block's 128 rows (X is tiny -> cache hits)
        float4 x = X4[n0 + tid];
        sa[tid] = x.x * ker[0] + x.y * ker[1] + x.z * ker[2] + x.w * ker[3];
        sb[tid] = x.x * ker[4] + x.y * ker[5] + x.z * ker[6] + x.w * ker[7];
    }
    __syncthreads();

    float4 so = make_float4(0.f, 0.f, 0.f, 0.f);
    float4 si = make_float4(0.f, 0.f, 0.f, 0.f);
    const float4* ro = Ro4 + (size_t)n0 * EE4 + e4;
    const float4* ri = Ri4 + (size_t)n0 * EE4 + e4;

#pragma unroll 4
    for (int j = 0; j < 128; j++) {
        float4 o = ro[(size_t)j * EE4];
        float4 i = ri[(size_t)j * EE4];
        float A = sa[j], B = sb[j];
        so.x += o.x * A; so.y += o.y * A; so.z += o.z * A; so.w += o.w * A;
        si.x += i.x * B; si.y += i.y * B; si.z += i.z * B; si.w += i.w * B;
    }

    float4 w = ev4[e4];
    int e = 4 * e4;
    atomicAdd(&g_uv[e + 0],      w.x * so.x);
    atomicAdd(&g_uv[e + 1],      w.y * so.y);
    atomicAdd(&g_uv[e + 2],      w.z * so.z);
    atomicAdd(&g_uv[e + 3],      w.w * so.w);
    atomicAdd(&g_uv[EE + e + 0], w.x * si.x);
    atomicAdd(&g_uv[EE + e + 1], w.y * si.y);
    atomicAdd(&g_uv[EE + e + 2], w.z * si.z);
    atomicAdd(&g_uv[EE + e + 3], w.w * si.w);
}

// ---------------- Phase 2: row reductions ----------------------------------
// out[n] = sum_e Ri[n,e]*u[e] + Ro[n,e]*v[e] + X[n].k2
// Block: 4 rows x half of E (2048 float4) = 256 KB -> fine scheduling grain.
// Partial row sums accumulated into memset-zeroed d_out via atomicAdd.
#define RPB 4
#define HALF 2048   // float4 per E-half
__global__ __launch_bounds__(256) void phase2(
    const float4* __restrict__ X4, const float* __restrict__ ker,
    const float4* __restrict__ Ri4, const float4* __restrict__ Ro4,
    float* __restrict__ out)
{
    __shared__ float red[RPB][256];
    int tid = threadIdx.x;
    int n0  = blockIdx.x * RPB;
    int h   = blockIdx.y;                 // E-half selector

    const float4* u4 = (const float4*)g_uv;
    const float4* v4 = u4 + EE4;

    float s[RPB];
#pragma unroll
    for (int r = 0; r < RPB; r++) s[r] = 0.f;

#pragma unroll 2
    for (int it = 0; it < HALF / 256; it++) {
        int e4 = h * HALF + it * 256 + tid;
        float4 u = u4[e4];                // L2 hits (u/v = 128 KB, hot)
        float4 v = v4[e4];
#pragma unroll
        for (int r = 0; r < RPB; r++) {
            float4 a = Ri4[(size_t)(n0 + r) * EE4 + e4];
            float4 b = Ro4[(size_t)(n0 + r) * EE4 + e4];
            s[r] += a.x * u.x + a.y * u.y + a.z * u.z + a.w * u.w
                  + b.x * v.x + b.y * v.y + b.z * v.z + b.w * v.w;
        }
    }

#pragma unroll
    for (int r = 0; r < RPB; r++) red[r][tid] = s[r];
    __syncthreads();
    for (int st = 128; st > 0; st >>= 1) {
        if (tid < st) {
#pragma unroll
            for (int r = 0; r < RPB; r++) red[r][tid] += red[r][tid + st];
        }
        __syncthreads();
    }
    if (tid < RPB) {
        float val = red[tid][0];
        if (h == 0) {   // add c = X.k2 exactly once per row
            float4 x = X4[n0 + tid];
            val += x.x * ker[8] + x.y * ker[9] + x.z * ker[10] + x.w * ker[11];
        }
        atomicAdd(&out[n0 + tid], val);
    }
}

extern "C" void kernel_launch(void* const* d_in, const int* in_sizes, int n_in,
                              void* d_out, int out_size) {
    const float4* X4  = (const float4*)d_in[0];
    const float4* ev4 = (const float4*)d_in[1];
    const float4* Ri4 = (const float4*)d_in[2];
    const float4* Ro4 = (const float4*)d_in[3];
    const float*  ker = (const float*)d_in[4];
    float* out = (float*)d_out;

    // Zero scratch (u,v) and output (accumulated via atomics) — memset nodes.
    void* uvptr = nullptr;
    cudaGetSymbolAddress(&uvptr, g_uv);
    cudaMemsetAsync(uvptr, 0, 2 * EE * sizeof(float));
    cudaMemsetAsync(out, 0, (size_t)out_size * sizeof(float));

    dim3 g1(EE4 / 128, NN / 128);   // (32, 64) = 2048 blocks, 0.5 MB each
    phase1<<<g1, 128>>>(X4, ker, Ri4, Ro4, ev4);

    dim3 g2(NN / RPB, 2);           // (2048, 2) = 4096 blocks, 256 KB each
    phase2<<<g2, 256>>>(X4, ker, Ri4, Ro4, out);
}

// round 6
// speedup vs baseline: 1.1028x; 1.1028x over previous
#include <cuda_runtime.h>

#define NN 8192
#define EE 16384
#define EE4 (EE / 4)

// u = e .* (Ro^T a) in g_uv[0..EE), v = e .* (Ri^T b) in g_uv[EE..2EE).
// Zeroed each launch via a cudaMemsetAsync node.
__device__ float g_uv[2 * EE];

// ---------------- Phase 1: column reductions -------------------------------
// u[e] = ev[e] * sum_n Ro[n,e]*a[n],  v[e] = ev[e] * sum_n Ri[n,e]*b[n]
// a = X.k0, b = X.k1 computed inline (X is 128 KB -> L2 hits).
// R4-proven shape: 256 threads, ONE scalar column per thread, 128-row chunk.
#define P1_CHUNK 128
__global__ __launch_bounds__(256) void phase1(
    const float4* __restrict__ X4, const float* __restrict__ ker,
    const float* __restrict__ Ri, const float* __restrict__ Ro,
    const float* __restrict__ ev)
{
    __shared__ float sa[P1_CHUNK], sb[P1_CHUNK];
    int tid = threadIdx.x;
    int e   = blockIdx.x * 256 + tid;
    int n0  = blockIdx.y * P1_CHUNK;

    if (tid < P1_CHUNK) {
        float4 x = X4[n0 + tid];
        sa[tid] = x.x * ker[0] + x.y * ker[1] + x.z * ker[2] + x.w * ker[3];
        sb[tid] = x.x * ker[4] + x.y * ker[5] + x.z * ker[6] + x.w * ker[7];
    }
    __syncthreads();

    const float* ro = Ro + (size_t)n0 * EE + e;
    const float* ri = Ri + (size_t)n0 * EE + e;
    float so = 0.0f, si = 0.0f;
#pragma unroll 8
    for (int j = 0; j < P1_CHUNK; j++) {
        so += __ldcs(ro + (size_t)j * EE) * sa[j];
        si += __ldcs(ri + (size_t)j * EE) * sb[j];
    }
    float w = ev[e];
    atomicAdd(&g_uv[e],      w * so);
    atomicAdd(&g_uv[EE + e], w * si);
}

// ---------------- Phase 2: row reductions ----------------------------------
// out[n] = sum_e Ri[n,e]*u[e] + Ro[n,e]*v[e] + X[n].k2
// R4-proven shape: one block per 4 rows, full E, float4 streaming loads.
#define RPB 4
__global__ __launch_bounds__(256) void phase2(
    const float4* __restrict__ X4, const float* __restrict__ ker,
    const float4* __restrict__ Ri4, const float4* __restrict__ Ro4,
    float* __restrict__ out)
{
    __shared__ float red[RPB][256];
    int tid = threadIdx.x;
    int n0  = blockIdx.x * RPB;

    const float4* u4 = (const float4*)g_uv;
    const float4* v4 = u4 + EE4;

    float s[RPB];
#pragma unroll
    for (int r = 0; r < RPB; r++) s[r] = 0.0f;

#pragma unroll 4
    for (int it = 0; it < EE4 / 256; it++) {
        int e4 = it * 256 + tid;
        float4 u = u4[e4];                 // hot in L2 (128 KB total)
        float4 v = v4[e4];
#pragma unroll
        for (int r = 0; r < RPB; r++) {
            float4 a = __ldcs(Ri4 + (size_t)(n0 + r) * EE4 + e4);
            float4 b = __ldcs(Ro4 + (size_t)(n0 + r) * EE4 + e4);
            s[r] += a.x * u.x + a.y * u.y + a.z * u.z + a.w * u.w
                  + b.x * v.x + b.y * v.y + b.z * v.z + b.w * v.w;
        }
    }

#pragma unroll
    for (int r = 0; r < RPB; r++) red[r][tid] = s[r];
    __syncthreads();
    for (int st = 128; st > 0; st >>= 1) {
        if (tid < st) {
#pragma unroll
            for (int r = 0; r < RPB; r++) red[r][tid] += red[r][tid + st];
        }
        __syncthreads();
    }
    if (tid < RPB) {
        float4 x = X4[n0 + tid];
        out[n0 + tid] = red[tid][0]
                      + x.x * ker[8] + x.y * ker[9] + x.z * ker[10] + x.w * ker[11];
    }
}

extern "C" void kernel_launch(void* const* d_in, const int* in_sizes, int n_in,
                              void* d_out, int out_size) {
    const float4* X4  = (const float4*)d_in[0];
    const float*  ev  = (const float*)d_in[1];
    const float*  Ri  = (const float*)d_in[2];
    const float*  Ro  = (const float*)d_in[3];
    const float*  ker = (const float*)d_in[4];
    float* out = (float*)d_out;

    void* uvptr = nullptr;
    cudaGetSymbolAddress(&uvptr, g_uv);
    cudaMemsetAsync(uvptr, 0, 2 * EE * sizeof(float));

    dim3 g1(EE / 256, NN / P1_CHUNK);                  // (64, 64)
    phase1<<<g1, 256>>>(X4, ker, Ri, Ro, ev);

    phase2<<<NN / RPB, 256>>>(X4, ker,
                              (const float4*)Ri, (const float4*)Ro, out);
}

// round 8
// speedup vs baseline: 1.1260x; 1.0210x over previous
#include <cuda_runtime.h>

#define NN 8192
#define EE 16384
#define EE4 (EE / 4)

// u = e .* (Ro^T a) in g_uv[0..EE), v = e .* (Ri^T b) in g_uv[EE..2EE).
__device__ float g_uv[2 * EE];
__device__ unsigned int g_ticket;   // phase2 tile dispatcher

// ---------------- Phase 1: column reductions -------------------------------
// u[e] = ev[e] * sum_n Ro[n,e]*a[n],  v[e] = ev[e] * sum_n Ri[n,e]*b[n]
// Row chunks REVERSED: high blockIdx.y (executed last) handles LOW rows, and
// those final P1_KEEP chunks use default (L2-allocating) loads so phase2's
// ascending scan hits them in L2. Everything else streams with __ldcs.
#define P1_CHUNK 128
#define P1_NCHUNK (NN / P1_CHUNK)      // 64
#define P1_KEEP 8                      // last 8 chunks (1024 rows, ~128MB) kept in L2
__global__ __launch_bounds__(256) void phase1(
    const float4* __restrict__ X4, const float* __restrict__ ker,
    const float* __restrict__ Ri, const float* __restrict__ Ro,
    const float* __restrict__ ev)
{
    __shared__ float sa[P1_CHUNK], sb[P1_CHUNK];
    int tid = threadIdx.x;
    int e   = blockIdx.x * 256 + tid;
    int yc  = blockIdx.y;
    int n0  = (P1_NCHUNK - 1 - yc) * P1_CHUNK;   // reversed row mapping

    if (tid < P1_CHUNK) {
        float4 x = X4[n0 + tid];
        sa[tid] = x.x * ker[0] + x.y * ker[1] + x.z * ker[2] + x.w * ker[3];
        sb[tid] = x.x * ker[4] + x.y * ker[5] + x.z * ker[6] + x.w * ker[7];
    }
    __syncthreads();

    const float* ro = Ro + (size_t)n0 * EE + e;
    const float* ri = Ri + (size_t)n0 * EE + e;
    float so = 0.0f, si = 0.0f;

    if (yc >= P1_NCHUNK - P1_KEEP) {
        // Final chunks: default loads -> lines stay resident in L2 for phase2.
#pragma unroll 8
        for (int j = 0; j < P1_CHUNK; j++) {
            so += ro[(size_t)j * EE] * sa[j];
            si += ri[(size_t)j * EE] * sb[j];
        }
    } else {
        // Bulk: streaming loads, evict-first.
#pragma unroll 8
        for (int j = 0; j < P1_CHUNK; j++) {
            so += __ldcs(ro + (size_t)j * EE) * sa[j];
            si += __ldcs(ri + (size_t)j * EE) * sb[j];
        }
    }
    float w = ev[e];
    atomicAdd(&g_uv[e],      w * so);
    atomicAdd(&g_uv[EE + e], w * si);
}

// ---------------- Phase 2: row reductions (persistent, ticket dispatch) ----
// out[n] = sum_e Ri[n,e]*u[e] + Ro[n,e]*v[e] + X[n].k2
// 592 resident blocks pull 4-row tiles from g_ticket in ascending order:
// perfect balance (no wave tail) and low rows first (L2 handoff from phase1).
#define RPB 4
#define NTILES (NN / RPB)              // 2048
#define P2_BLOCKS (148 * 4)
__global__ __launch_bounds__(256) void phase2(
    const float4* __restrict__ X4, const float* __restrict__ ker,
    const float4* __restrict__ Ri4, const float4* __restrict__ Ro4,
    float* __restrict__ out)
{
    __shared__ float red[RPB][256];
    __shared__ int sTile;
    int tid = threadIdx.x;

    const float4* u4 = (const float4*)g_uv;
    const float4* v4 = u4 + EE4;

    for (;;) {
        if (tid == 0) sTile = (int)atomicAdd(&g_ticket, 1u);
        __syncthreads();
        int tile = sTile;
        if (tile >= NTILES) break;
        int n0 = tile * RPB;

        float s[RPB];
#pragma unroll
        for (int r = 0; r < RPB; r++) s[r] = 0.0f;

#pragma unroll 4
        for (int it = 0; it < EE4 / 256; it++) {
            int e4 = it * 256 + tid;
            float4 u = u4[e4];             // hot in L2 (128 KB total)
            float4 v = v4[e4];
#pragma unroll
            for (int r = 0; r < RPB; r++) {
                float4 a = __ldcs(Ri4 + (size_t)(n0 + r) * EE4 + e4);
                float4 b = __ldcs(Ro4 + (size_t)(n0 + r) * EE4 + e4);
                s[r] += a.x * u.x + a.y * u.y + a.z * u.z + a.w * u.w
                      + b.x * v.x + b.y * v.y + b.z * v.z + b.w * v.w;
            }
        }

#pragma unroll
        for (int r = 0; r < RPB; r++) red[r][tid] = s[r];
        __syncthreads();
        for (int st = 128; st > 0; st >>= 1) {
            if (tid < st) {
#pragma unroll
                for (int r = 0; r < RPB; r++) red[r][tid] += red[r][tid + st];
            }
            __syncthreads();
        }
        if (tid < RPB) {
            float4 x = X4[n0 + tid];
            out[n0 + tid] = red[tid][0]
                          + x.x * ker[8] + x.y * ker[9] + x.z * ker[10] + x.w * ker[11];
        }
        __syncthreads();   // red/sTile safe to reuse
    }
}

extern "C" void kernel_launch(void* const* d_in, const int* in_sizes, int n_in,
                              void* d_out, int out_size) {
    const float4* X4  = (const float4*)d_in[0];
    const float*  ev  = (const float*)d_in[1];
    const float*  Ri  = (const float*)d_in[2];
    const float*  Ro  = (const float*)d_in[3];
    const float*  ker = (const float*)d_in[4];
    float* out = (float*)d_out;

    void* uvptr = nullptr;
    cudaGetSymbolAddress(&uvptr, g_uv);
    cudaMemsetAsync(uvptr, 0, 2 * EE * sizeof(float));
    void* tkptr = nullptr;
    cudaGetSymbolAddress(&tkptr, g_ticket);
    cudaMemsetAsync(tkptr, 0, sizeof(unsigned int));

    dim3 g1(EE / 256, P1_NCHUNK);                  // (64, 64)
    phase1<<<g1, 256>>>(X4, ker, Ri, Ro, ev);

    phase2<<<P2_BLOCKS, 256>>>(X4, ker,
                               (const float4*)Ri, (const float4*)Ro, out);
}